// round 4
// baseline (speedup 1.0000x reference)
#include <cuda_runtime.h>
#include <math_constants.h>
#include <cstdint>

#define Bb 4
#define Ss 1024
#define Dd 1024
#define Hh 16
#define DKk 64
#define DFFf 4096
#define EPSl 1e-5f

#define X_ELEMS   ((size_t)Bb * Ss * Dd)
#define ATT_ELEMS ((size_t)Bb * Hh * Ss * Ss)

// ---------------- scratch ----------------
__device__ float g_q[X_ELEMS];
__device__ float g_k[X_ELEMS];
__device__ float g_v[X_ELEMS];
__device__ float g_ctx[X_ELEMS];
__device__ float g_t1[X_ELEMS];
__device__ float g_x1[X_ELEMS];
__device__ float g_ffh[(size_t)Bb * Ss * DFFf];
__device__ float g_attn_fb[ATT_ELEMS];
__device__ float g_x_fb[X_ELEMS];

// ---------------- helpers ----------------
__device__ __forceinline__ void cp_async16(void* smem_dst, const void* gsrc) {
    uint32_t s = (uint32_t)__cvta_generic_to_shared(smem_dst);
    asm volatile("cp.async.cg.shared.global [%0], [%1], 16;" :: "r"(s), "l"(gsrc));
}
__device__ __forceinline__ void cp_commit() {
    asm volatile("cp.async.commit_group;");
}
template<int N>
__device__ __forceinline__ void cp_wait() {
    asm volatile("cp.async.wait_group %0;" :: "n"(N));
}
__device__ __forceinline__ uint32_t f2tf(uint32_t x) {
    uint32_t r;
    asm("cvt.rna.tf32.f32 %0, %1;" : "=r"(r) : "f"(__uint_as_float(x)));
    return r;
}
__device__ __forceinline__ void ldsm_x4(uint32_t r[4], uint32_t saddr) {
    asm volatile("ldmatrix.sync.aligned.m8n8.x4.shared.b16 {%0,%1,%2,%3}, [%4];"
                 : "=r"(r[0]), "=r"(r[1]), "=r"(r[2]), "=r"(r[3]) : "r"(saddr));
}
__device__ __forceinline__ void ldsm_x2(uint32_t r[2], uint32_t saddr) {
    asm volatile("ldmatrix.sync.aligned.m8n8.x2.shared.b16 {%0,%1}, [%2];"
                 : "=r"(r[0]), "=r"(r[1]) : "r"(saddr));
}
__device__ __forceinline__ void mma_tf32(float c[4], const uint32_t a[4], const uint32_t b[2]) {
    asm volatile(
        "mma.sync.aligned.m16n8k8.row.col.f32.tf32.tf32.f32 "
        "{%0,%1,%2,%3}, {%4,%5,%6,%7}, {%8,%9}, {%0,%1,%2,%3};"
        : "+f"(c[0]), "+f"(c[1]), "+f"(c[2]), "+f"(c[3])
        : "r"(a[0]), "r"(a[1]), "r"(a[2]), "r"(a[3]), "r"(b[0]), "r"(b[1]));
}

// MODE: 0 = plain GEMM. 1 = scores (A=Q head, B^T=K head, C=attn[z]).
// 2 = ctx (A=attn[z], B=V head, C=ctx head slice). 3 = QKV batched (z picks B/bias/C).
template<int BM, int BN, int WM, int WN, bool TRANSB, bool BIAS, bool RELU, int MODE>
__global__ void __launch_bounds__(256)
tf32_gemm(const float* __restrict__ A,
          const float* __restrict__ B0, const float* __restrict__ B1p, const float* __restrict__ B2p,
          const float* __restrict__ bias0, const float* __restrict__ bias1, const float* __restrict__ bias2,
          float* __restrict__ C0, float* __restrict__ C1p, float* __restrict__ C2p,
          int K, int lda, int ldb, int ldc, float scale) {
    constexpr int BK = 16;
    constexpr int STAGES = 4;
    constexpr int WCOLS = BN / WN;
    constexpr int AM = WM / 16;
    constexpr int BNT = WN / 8;
    constexpr int ASTRIDE = BK + 4;                        // 20 floats
    constexpr int BSTRIDE = TRANSB ? (BK + 4) : (BN + 4);
    constexpr int SA = BM * ASTRIDE;
    constexpr int SB = TRANSB ? (BN * ASTRIDE) : (BK * (BN + 4));
    constexpr int LDA_V = BM * BK / (4 * 256);
    constexpr int LDB_V = (TRANSB ? BN * BK : BK * BN) / (4 * 256);

    extern __shared__ float smem[];
    float* As = smem;
    float* Bs = smem + STAGES * SA;

    const int tid = threadIdx.x;
    const int warp = tid >> 5, lane = tid & 31;
    const int grp = lane >> 2, tig = lane & 3;
    const int wm = (warp / WCOLS) * WM;
    const int wn = (warp % WCOLS) * WN;
    const int row0 = blockIdx.y * BM;
    const int col0 = blockIdx.x * BN;
    const int z = blockIdx.z;

    const float* Bsel = B0;
    const float* biasSel = bias0;
    float* Csel = C0;
    if (MODE == 3) {
        if (z == 1) { Bsel = B1p; biasSel = bias1; Csel = C1p; }
        else if (z == 2) { Bsel = B2p; biasSel = bias2; Csel = C2p; }
    }

    size_t offA = 0, offB = 0, offC = 0;
    if (MODE == 1) {
        size_t ho = (size_t)(z >> 4) * Ss * Dd + (size_t)(z & 15) * DKk;
        offA = ho; offB = ho; offC = (size_t)z * Ss * Ss;
    }
    if (MODE == 2) {
        size_t ho = (size_t)(z >> 4) * Ss * Dd + (size_t)(z & 15) * DKk;
        offA = (size_t)z * Ss * Ss; offB = ho; offC = ho;
    }
    const float* Ag = A + offA;
    const float* Bg = Bsel + offB;
    float* Cg = Csel + offC;

    auto copyA = [&](int stage, int k0) {
#pragma unroll
        for (int i = 0; i < LDA_V; i++) {
            int flat = tid + i * 256;
            int r = flat >> 2, c4 = flat & 3;
            cp_async16(&As[stage * SA + r * ASTRIDE + c4 * 4],
                       &Ag[(size_t)(row0 + r) * lda + k0 + c4 * 4]);
        }
    };
    auto copyB = [&](int stage, int k0) {
#pragma unroll
        for (int i = 0; i < LDB_V; i++) {
            int flat = tid + i * 256;
            if (TRANSB) {
                int n = flat >> 2, c4 = flat & 3;
                cp_async16(&Bs[stage * SB + n * BSTRIDE + c4 * 4],
                           &Bg[(size_t)(col0 + n) * ldb + k0 + c4 * 4]);
            } else {
                constexpr int C4 = BN / 4;
                int r = flat / C4, c4 = flat % C4;
                cp_async16(&Bs[stage * SB + r * BSTRIDE + c4 * 4],
                           &Bg[(size_t)(k0 + r) * ldb + col0 + c4 * 4]);
            }
        }
    };

    // ldmatrix per-thread row offsets (float units)
    const uint32_t as_base = (uint32_t)__cvta_generic_to_shared(As);
    const uint32_t bs_base = (uint32_t)__cvta_generic_to_shared(Bs);
    const int a_thr_off = (wm + ((lane >> 3) & 1) * 8 + (lane & 7)) * ASTRIDE
                        + ((lane >> 4) ? 4 : 0);
    const int b_thr_off = TRANSB
        ? (wn + (lane & 7)) * BSTRIDE + (((lane >> 3) & 1) ? 4 : 0)
        : 0;

    float acc[AM][BNT][4];
#pragma unroll
    for (int i = 0; i < AM; i++)
#pragma unroll
        for (int j = 0; j < BNT; j++)
#pragma unroll
            for (int q = 0; q < 4; q++) acc[i][j][q] = 0.f;

    const int KT = K / BK;
    int fetch = 0;
    for (; fetch < STAGES - 1; fetch++) {
        copyA(fetch, fetch * BK);
        copyB(fetch, fetch * BK);
        cp_commit();
    }

    for (int kt = 0; kt < KT; kt++) {
        cp_wait<STAGES - 2>();
        __syncthreads();
        if (fetch < KT) {
            copyA(fetch % STAGES, fetch * BK);
            copyB(fetch % STAGES, fetch * BK);
            fetch++;
        }
        cp_commit();

        const int buf = kt % STAGES;
        const float* Bsb = &Bs[buf * SB];
#pragma unroll
        for (int ks = 0; ks < BK; ks += 8) {
            uint32_t af[AM][4];
            uint32_t bf[BNT][2];
#pragma unroll
            for (int i = 0; i < AM; i++) {
                uint32_t addr = as_base + 4u * (buf * SA + a_thr_off + i * 16 * ASTRIDE + ks);
                ldsm_x4(af[i], addr);
                af[i][0] = f2tf(af[i][0]); af[i][1] = f2tf(af[i][1]);
                af[i][2] = f2tf(af[i][2]); af[i][3] = f2tf(af[i][3]);
            }
#pragma unroll
            for (int j = 0; j < BNT; j++) {
                if (TRANSB) {
                    uint32_t addr = bs_base + 4u * (buf * SB + b_thr_off + j * 8 * BSTRIDE + ks);
                    ldsm_x2(bf[j], addr);
                } else {
                    int n = wn + j * 8 + grp;
                    bf[j][0] = __float_as_uint(Bsb[(ks + tig) * BSTRIDE + n]);
                    bf[j][1] = __float_as_uint(Bsb[(ks + tig + 4) * BSTRIDE + n]);
                }
                bf[j][0] = f2tf(bf[j][0]);
                bf[j][1] = f2tf(bf[j][1]);
            }
#pragma unroll
            for (int i = 0; i < AM; i++)
#pragma unroll
                for (int j = 0; j < BNT; j++)
                    mma_tf32(acc[i][j], af[i], bf[j]);
        }
    }

#pragma unroll
    for (int i = 0; i < AM; i++) {
        int r1 = row0 + wm + i * 16 + grp;
        int r2 = r1 + 8;
#pragma unroll
        for (int j = 0; j < BNT; j++) {
            int cc = col0 + wn + j * 8 + tig * 2;
            float b0v = 0.f, b1v = 0.f;
            if (BIAS) { b0v = biasSel[cc]; b1v = biasSel[cc + 1]; }
            float v0 = acc[i][j][0] * scale + b0v;
            float v1 = acc[i][j][1] * scale + b1v;
            float v2 = acc[i][j][2] * scale + b0v;
            float v3 = acc[i][j][3] * scale + b1v;
            if (RELU) {
                v0 = fmaxf(v0, 0.f); v1 = fmaxf(v1, 0.f);
                v2 = fmaxf(v2, 0.f); v3 = fmaxf(v3, 0.f);
            }
            *(float2*)&Cg[(size_t)r1 * ldc + cc] = make_float2(v0, v1);
            *(float2*)&Cg[(size_t)r2 * ldc + cc] = make_float2(v2, v3);
        }
    }
}

// ---------------- row softmax (1024 cols) -------------------------------------
__global__ void softmax_kernel(float* __restrict__ attn) {
    const size_t row = blockIdx.x;
    float4* p = (float4*)(attn + row * Ss);
    const int tid = threadIdx.x;  // 256
    __shared__ float red[8];
    float4 v = p[tid];
    float m = fmaxf(fmaxf(v.x, v.y), fmaxf(v.z, v.w));
#pragma unroll
    for (int o = 16; o > 0; o >>= 1) m = fmaxf(m, __shfl_xor_sync(~0u, m, o));
    if ((tid & 31) == 0) red[tid >> 5] = m;
    __syncthreads();
    m = red[tid & 7];
#pragma unroll
    for (int o = 4; o > 0; o >>= 1) m = fmaxf(m, __shfl_xor_sync(~0u, m, o));
    v.x = __expf(v.x - m); v.y = __expf(v.y - m);
    v.z = __expf(v.z - m); v.w = __expf(v.w - m);
    float s = v.x + v.y + v.z + v.w;
#pragma unroll
    for (int o = 16; o > 0; o >>= 1) s += __shfl_xor_sync(~0u, s, o);
    __syncthreads();
    if ((tid & 31) == 0) red[tid >> 5] = s;
    __syncthreads();
    s = red[tid & 7];
#pragma unroll
    for (int o = 4; o > 0; o >>= 1) s += __shfl_xor_sync(~0u, s, o);
    float inv = 1.f / s;
    v.x *= inv; v.y *= inv; v.z *= inv; v.w *= inv;
    p[tid] = v;
}

// ---------------- residual add + layernorm (1024 cols) ------------------------
__global__ void add_ln_kernel(const float* __restrict__ a,
                              const float* __restrict__ bres,
                              const float* __restrict__ g,
                              const float* __restrict__ be,
                              float* __restrict__ out) {
    const size_t row = blockIdx.x;
    const float4* pa = (const float4*)(a + row * Dd);
    const float4* pb = (const float4*)(bres + row * Dd);
    float4* po = (float4*)(out + row * Dd);
    const int tid = threadIdx.x;  // 256
    __shared__ float red[8];
    float4 va = pa[tid], vb = pb[tid];
    float4 v = make_float4(va.x + vb.x, va.y + vb.y, va.z + vb.z, va.w + vb.w);
    float s = v.x + v.y + v.z + v.w;
#pragma unroll
    for (int o = 16; o > 0; o >>= 1) s += __shfl_xor_sync(~0u, s, o);
    if ((tid & 31) == 0) red[tid >> 5] = s;
    __syncthreads();
    s = red[tid & 7];
#pragma unroll
    for (int o = 4; o > 0; o >>= 1) s += __shfl_xor_sync(~0u, s, o);
    const float mu = s * (1.f / Dd);
    float q = (v.x - mu) * (v.x - mu) + (v.y - mu) * (v.y - mu)
            + (v.z - mu) * (v.z - mu) + (v.w - mu) * (v.w - mu);
#pragma unroll
    for (int o = 16; o > 0; o >>= 1) q += __shfl_xor_sync(~0u, q, o);
    __syncthreads();
    if ((tid & 31) == 0) red[tid >> 5] = q;
    __syncthreads();
    q = red[tid & 7];
#pragma unroll
    for (int o = 4; o > 0; o >>= 1) q += __shfl_xor_sync(~0u, q, o);
    const float inv = rsqrtf(q * (1.f / Dd) + EPSl);
    float4 vg = ((const float4*)g)[tid], vbe = ((const float4*)be)[tid];
    po[tid] = make_float4((v.x - mu) * inv * vg.x + vbe.x,
                          (v.y - mu) * inv * vg.y + vbe.y,
                          (v.z - mu) * inv * vg.z + vbe.z,
                          (v.w - mu) * inv * vg.w + vbe.w);
}

// ---------------- launch -------------------------------------------------------
extern "C" void kernel_launch(void* const* d_in, const int* in_sizes, int n_in,
                              void* d_out, int out_size) {
    const float* x  = (const float*)d_in[0];
    const float* Wq = (const float*)d_in[1];
    const float* bq = (const float*)d_in[2];
    const float* Wk = (const float*)d_in[3];
    const float* bk = (const float*)d_in[4];
    const float* Wv = (const float*)d_in[5];
    const float* bv = (const float*)d_in[6];
    const float* Wo = (const float*)d_in[7];
    const float* bo = (const float*)d_in[8];
    const float* W1 = (const float*)d_in[9];
    const float* b1 = (const float*)d_in[10];
    const float* W2 = (const float*)d_in[11];
    const float* b2 = (const float*)d_in[12];
    const float* g1 = (const float*)d_in[13];
    const float* be1 = (const float*)d_in[14];
    const float* g2 = (const float*)d_in[15];
    const float* be2 = (const float*)d_in[16];

    float* q;   cudaGetSymbolAddress((void**)&q,   g_q);
    float* k;   cudaGetSymbolAddress((void**)&k,   g_k);
    float* v;   cudaGetSymbolAddress((void**)&v,   g_v);
    float* ctx; cudaGetSymbolAddress((void**)&ctx, g_ctx);
    float* t1;  cudaGetSymbolAddress((void**)&t1,  g_t1);
    float* x1;  cudaGetSymbolAddress((void**)&x1,  g_x1);
    float* ffh; cudaGetSymbolAddress((void**)&ffh, g_ffh);
    float* attn_fb; cudaGetSymbolAddress((void**)&attn_fb, g_attn_fb);
    float* x_fb;    cudaGetSymbolAddress((void**)&x_fb,    g_x_fb);

    float* out_x;
    float* out_attn;
    const size_t osz = (size_t)out_size;
    if (osz >= X_ELEMS + ATT_ELEMS) {
        out_x = (float*)d_out;
        out_attn = (float*)d_out + X_ELEMS;
    } else if (osz == ATT_ELEMS) {
        out_x = x_fb;
        out_attn = (float*)d_out;
    } else {
        out_x = (float*)d_out;
        out_attn = attn_fb;
    }

    const int M = Bb * Ss;  // 4096
    dim3 blk(256);

    const int smem_proj   = 4 * (128 * 20 + 16 * 132) * 4;  // 74,752 B
    const int smem_scores = 4 * (128 * 20 + 128 * 20) * 4;  // 81,920 B
    const int smem_ctx    = 4 * (128 * 20 + 16 * 68) * 4;   // 58,368 B

    auto* kqkv   = tf32_gemm<128,128,64,32,false,true,false,3>;
    auto* kproj  = tf32_gemm<128,128,64,32,false,true,false,0>;
    auto* kprojr = tf32_gemm<128,128,64,32,false,true,true,0>;
    auto* kscore = tf32_gemm<128,128,64,32,true,false,false,1>;
    auto* kctx   = tf32_gemm<128,64,64,16,false,false,false,2>;
    cudaFuncSetAttribute(kqkv,   cudaFuncAttributeMaxDynamicSharedMemorySize, smem_proj);
    cudaFuncSetAttribute(kproj,  cudaFuncAttributeMaxDynamicSharedMemorySize, smem_proj);
    cudaFuncSetAttribute(kprojr, cudaFuncAttributeMaxDynamicSharedMemorySize, smem_proj);
    cudaFuncSetAttribute(kscore, cudaFuncAttributeMaxDynamicSharedMemorySize, smem_scores);
    cudaFuncSetAttribute(kctx,   cudaFuncAttributeMaxDynamicSharedMemorySize, smem_ctx);

    // QKV projections: one launch, z selects weight/bias/output
    kqkv<<<dim3(Dd/128, M/128, 3), blk, smem_proj>>>(
        x, Wq, Wk, Wv, bq, bk, bv, q, k, v, Dd, Dd, Dd, Dd, 1.f);

    // scores: per (b,h): [1024,64] @ [1024,64]^T / 8
    kscore<<<dim3(Ss/128, Ss/128, Bb*Hh), blk, smem_scores>>>(
        q, k, nullptr, nullptr, nullptr, nullptr, nullptr,
        out_attn, nullptr, nullptr, DKk, Dd, Dd, Ss, 0.125f);

    softmax_kernel<<<(unsigned)(Bb * Hh * Ss), blk>>>(out_attn);

    // ctx: per (b,h): [1024,1024] @ [1024,64]
    kctx<<<dim3(1, Ss/128, Bb*Hh), blk, smem_ctx>>>(
        out_attn, v, nullptr, nullptr, nullptr, nullptr, nullptr,
        ctx, nullptr, nullptr, Ss, Ss, Dd, Dd, 1.f);

    // output projection + LN1
    kproj<<<dim3(Dd/128, M/128), blk, smem_proj>>>(
        ctx, Wo, nullptr, nullptr, bo, nullptr, nullptr,
        t1, nullptr, nullptr, Dd, Dd, Dd, Dd, 1.f);
    add_ln_kernel<<<M, blk>>>(x, t1, g1, be1, x1);

    // FFN + LN2
    kprojr<<<dim3(DFFf/128, M/128), blk, smem_proj>>>(
        x1, W1, nullptr, nullptr, b1, nullptr, nullptr,
        ffh, nullptr, nullptr, Dd, Dd, DFFf, DFFf, 1.f);
    kproj<<<dim3(Dd/128, M/128), blk, smem_proj>>>(
        ffh, W2, nullptr, nullptr, b2, nullptr, nullptr,
        t1, nullptr, nullptr, DFFf, DFFf, Dd, Dd, 1.f);
    add_ln_kernel<<<M, blk>>>(x1, t1, g2, be2, out_x);
}